// round 6
// baseline (speedup 1.0000x reference)
#include <cuda_runtime.h>
#include <cuda_bf16.h>

// Problem constants (fixed by the reference): N=100000 nodes, IN_F=128, HID=32, E=3200000.
#define MAX_N 100000
#define MAX_E 3200000
#define HID 32

// Scratch (device globals: allocation-free rule). 16B-aligned for float4 access.
__device__ int   g_is64;                              // edge_index dtype flag (1 = int64)
__device__ int   g_src[MAX_E];                        // converted int32 source indices
__device__ int   g_dst[MAX_E];                        // converted int32 dest indices
__device__ float g_deg[MAX_N];                        // degree (init 1.0 for self-loop)
__device__ __align__(16) float g_h[MAX_N * HID];      // h' = dinv[n] * (x[n] @ W1)
__device__ __align__(16) float g_A[MAX_N * HID];      // accumulator, init = h' (absorbs self-loop)

// ---------------------------------------------------------------------------
// K-detect: decide whether edge_index is int64 or int32.
// int64 values < 2^31 -> every odd 32-bit word (the high half) is 0.
// Genuine int32 node ids in [0,100000) are ~never 0 for 128 consecutive odds.
__global__ void k_detect(const unsigned int* __restrict__ ei_raw) {
    if (threadIdx.x == 0 && blockIdx.x == 0) {
        int is64 = 1;
        #pragma unroll 1
        for (int i = 0; i < 128; i++)
            if (ei_raw[2 * i + 1] != 0u) { is64 = 0; break; }
        g_is64 = is64;
    }
}

// K-convert: materialize int32 src/dst regardless of storage dtype.
__global__ void k_convert(const void* __restrict__ ei_raw, int E) {
    int e = blockIdx.x * blockDim.x + threadIdx.x;
    if (e >= E) return;
    if (g_is64) {
        const long long* p = (const long long*)ei_raw;
        g_src[e] = (int)p[e];
        g_dst[e] = (int)p[E + e];
    } else {
        const int* p = (const int*)ei_raw;
        g_src[e] = p[e];
        g_dst[e] = p[E + e];
    }
}

// ---------------------------------------------------------------------------
// K0: deg[n] = 1.0 (self-loop weight)
__global__ void k_init_deg(int n) {
    int i = blockIdx.x * blockDim.x + threadIdx.x;
    if (i < n) g_deg[i] = 1.0f;
}

// K1: deg[dst] += w  over all edges
__global__ void k_deg(const float* __restrict__ ew, int E) {
    int e = blockIdx.x * blockDim.x + threadIdx.x;
    if (e < E) atomicAdd(&g_deg[g_dst[e]], __ldg(&ew[e]));
}

// ---------------------------------------------------------------------------
// K2: h'[n][j] = rsqrt(deg[n]) * sum_k x[n][k] * W1[k][j];  A = h'
// Block: 256 threads = 8 warps, tile of 64 nodes. lane = output feature j.
__global__ void __launch_bounds__(256) k_gemm(const float* __restrict__ x,
                                              const float* __restrict__ W1, int n) {
    __shared__ float  W1s[128 * HID];     // 16 KB
    __shared__ float4 xs4[64 * 32];       // 32 KB : 64 nodes x 128 floats

    int tid = threadIdx.x;
    #pragma unroll
    for (int i = 0; i < 16; i++) W1s[tid + i * 256] = W1[tid + i * 256];

    int nodeBase = blockIdx.x * 64;
    const float4* x4 = (const float4*)x;
    for (int i = tid; i < 64 * 32; i += 256) {
        int node = nodeBase + (i >> 5);
        xs4[i] = (node < n) ? __ldg(&x4[(size_t)node * 32 + (i & 31)])
                            : make_float4(0.f, 0.f, 0.f, 0.f);
    }
    __syncthreads();

    int warp = tid >> 5, lane = tid & 31;
    float acc[8];
    #pragma unroll
    for (int m = 0; m < 8; m++) acc[m] = 0.f;

    #pragma unroll 4
    for (int k4 = 0; k4 < 32; k4++) {
        float w0 = W1s[(k4 * 4 + 0) * HID + lane];
        float w1 = W1s[(k4 * 4 + 1) * HID + lane];
        float w2 = W1s[(k4 * 4 + 2) * HID + lane];
        float w3 = W1s[(k4 * 4 + 3) * HID + lane];
        #pragma unroll
        for (int m = 0; m < 8; m++) {
            float4 xv = xs4[(warp * 8 + m) * 32 + k4];   // same addr for all lanes: broadcast
            acc[m] = fmaf(xv.x, w0, acc[m]);
            acc[m] = fmaf(xv.y, w1, acc[m]);
            acc[m] = fmaf(xv.z, w2, acc[m]);
            acc[m] = fmaf(xv.w, w3, acc[m]);
        }
    }

    #pragma unroll
    for (int m = 0; m < 8; m++) {
        int node = nodeBase + warp * 8 + m;
        if (node < n) {
            float dinv = rsqrtf(g_deg[node]);   // deg >= 1 always
            float v = dinv * acc[m];
            g_h[(size_t)node * HID + lane] = v;
            g_A[(size_t)node * HID + lane] = v;
        }
    }
}

// ---------------------------------------------------------------------------
// K3: edge scatter.  A[dst] += w * h'[src]  -- 8 threads per edge, float4 each.
// Native float4 atomicAdd (sm_90+) -> 128-bit RED, quarter the LTS atomic ops.
__global__ void __launch_bounds__(256) k_edge(const float* __restrict__ ew, int E) {
    long long t = (long long)blockIdx.x * blockDim.x + threadIdx.x;
    if (t >= (long long)E * 8) return;
    int e = (int)(t >> 3);
    int c = (int)(t & 7);

    int src = __ldg(&g_src[e]);
    int dst = __ldg(&g_dst[e]);
    float w = __ldg(&ew[e]);

    const float4* hp = (const float4*)g_h;
    float4 hv = __ldg(&hp[(size_t)src * 8 + c]);

    float4* ap = reinterpret_cast<float4*>(g_A) + ((size_t)dst * 8 + c);
    atomicAdd(ap, make_float4(w * hv.x, w * hv.y, w * hv.z, w * hv.w));
}

// ---------------------------------------------------------------------------
// K4: out[n] = relu(dinv[n]*A[n][:] + b1) . W2 + b2    (warp per node)
__global__ void __launch_bounds__(256) k_final(const float* __restrict__ b1,
                                               const float* __restrict__ W2,
                                               const float* __restrict__ b2,
                                               float* __restrict__ out, int n) {
    int gwarp = (blockIdx.x * blockDim.x + threadIdx.x) >> 5;
    int lane = threadIdx.x & 31;
    if (gwarp >= n) return;
    float dinv = rsqrtf(g_deg[gwarp]);
    float v = dinv * g_A[(size_t)gwarp * HID + lane] + __ldg(&b1[lane]);
    v = fmaxf(v, 0.f) * __ldg(&W2[lane]);
    #pragma unroll
    for (int o = 16; o > 0; o >>= 1) v += __shfl_xor_sync(0xffffffff, v, o);
    if (lane == 0) out[gwarp] = v + __ldg(&b2[0]);
}

// ---------------------------------------------------------------------------
extern "C" void kernel_launch(void* const* d_in, const int* in_sizes, int n_in,
                              void* d_out, int out_size) {
    const float* x  = (const float*)d_in[0];
    const void*  ei = d_in[1];
    const float* ew = (const float*)d_in[2];
    const float* W1 = (const float*)d_in[3];
    const float* b1 = (const float*)d_in[4];
    const float* W2 = (const float*)d_in[5];
    const float* b2 = (const float*)d_in[6];
    float* out = (float*)d_out;

    int n = in_sizes[0] / 128;       // N nodes
    int E = in_sizes[2];             // edges (edge_weight count)

    k_detect<<<1, 32>>>((const unsigned int*)ei);
    k_convert<<<(E + 255) / 256, 256>>>(ei, E);
    k_init_deg<<<(n + 255) / 256, 256>>>(n);
    k_deg<<<(E + 255) / 256, 256>>>(ew, E);
    k_gemm<<<(n + 63) / 64, 256>>>(x, W1, n);

    long long work = (long long)E * 8;
    k_edge<<<(int)((work + 255) / 256), 256>>>(ew, E);

    k_final<<<(n + 7) / 8, 256>>>(b1, W2, b2, out, n);
}

// round 7
// speedup vs baseline: 1.5397x; 1.5397x over previous
#include <cuda_runtime.h>
#include <cuda_bf16.h>

// Problem constants (fixed by the reference): N=100000 nodes, IN_F=128, HID=32, E=3200000.
#define MAX_N 100000
#define MAX_E 3200000
#define HID 32

// Scratch (device globals: allocation-free rule). 16B-aligned for vector access.
__device__ int   g_is64;                              // edge_index dtype flag (1 = int64)
__device__ __align__(16) int2  g_sd[MAX_E];           // packed (src, dst) int32 pairs
__device__ float g_deg[MAX_N];                        // degree (init 1.0 for self-loop)
__device__ __align__(16) float g_h[MAX_N * HID];      // raw x@W1, then h' = dinv * (x@W1)
__device__ __align__(16) float g_A[MAX_N * HID];      // accumulator, init = h' (absorbs self-loop)

// ---------------------------------------------------------------------------
// K-detect: int64 vs int32 edge_index. int64 values < 2^31 -> odd 32-bit words all 0.
__global__ void k_detect(const unsigned int* __restrict__ ei_raw) {
    if (threadIdx.x == 0 && blockIdx.x == 0) {
        int is64 = 1;
        #pragma unroll 1
        for (int i = 0; i < 128; i++)
            if (ei_raw[2 * i + 1] != 0u) { is64 = 0; break; }
        g_is64 = is64;
    }
}

// K0: deg[n] = 1.0 (self-loop weight)
__global__ void k_init_deg(int n) {
    int i = blockIdx.x * blockDim.x + threadIdx.x;
    if (i < n) g_deg[i] = 1.0f;
}

// ---------------------------------------------------------------------------
// K-fused: block-range split.
//   blocks [0, G)        : raw GEMM tile  g_h[n] = x[n] @ W1   (64 nodes/block)
//   blocks [G, G+C)      : edge-index convert -> g_sd, deg[dst] += w
// The two halves are independent; atomic-bound convert hides under FMA-bound GEMM.
__global__ void __launch_bounds__(256) k_fused(const float* __restrict__ x,
                                               const float* __restrict__ W1,
                                               const void*  __restrict__ ei_raw,
                                               const float* __restrict__ ew,
                                               int n, int E, int G) {
    if (blockIdx.x >= (unsigned)G) {
        // ---- convert + degree ----
        int e = (blockIdx.x - G) * 256 + threadIdx.x;
        if (e < E) {
            int src, dst;
            if (g_is64) {
                const long long* p = (const long long*)ei_raw;
                src = (int)p[e];
                dst = (int)p[E + e];
            } else {
                const int* p = (const int*)ei_raw;
                src = p[e];
                dst = p[E + e];
            }
            g_sd[e] = make_int2(src, dst);
            atomicAdd(&g_deg[dst], __ldg(&ew[e]));
        }
        return;
    }

    // ---- GEMM tile: 8 warps, 64 nodes, lane = output feature ----
    __shared__ float  W1s[128 * HID];     // 16 KB
    __shared__ float4 xs4[64 * 32];       // 32 KB : 64 nodes x 128 floats

    int tid = threadIdx.x;
    #pragma unroll
    for (int i = 0; i < 16; i++) W1s[tid + i * 256] = W1[tid + i * 256];

    int nodeBase = blockIdx.x * 64;
    const float4* x4 = (const float4*)x;
    for (int i = tid; i < 64 * 32; i += 256) {
        int node = nodeBase + (i >> 5);
        xs4[i] = (node < n) ? __ldg(&x4[(size_t)node * 32 + (i & 31)])
                            : make_float4(0.f, 0.f, 0.f, 0.f);
    }
    __syncthreads();

    int warp = tid >> 5, lane = tid & 31;
    float acc[8];
    #pragma unroll
    for (int m = 0; m < 8; m++) acc[m] = 0.f;

    #pragma unroll 4
    for (int k4 = 0; k4 < 32; k4++) {
        float w0 = W1s[(k4 * 4 + 0) * HID + lane];
        float w1 = W1s[(k4 * 4 + 1) * HID + lane];
        float w2 = W1s[(k4 * 4 + 2) * HID + lane];
        float w3 = W1s[(k4 * 4 + 3) * HID + lane];
        #pragma unroll
        for (int m = 0; m < 8; m++) {
            float4 xv = xs4[(warp * 8 + m) * 32 + k4];   // same addr all lanes: broadcast
            acc[m] = fmaf(xv.x, w0, acc[m]);
            acc[m] = fmaf(xv.y, w1, acc[m]);
            acc[m] = fmaf(xv.z, w2, acc[m]);
            acc[m] = fmaf(xv.w, w3, acc[m]);
        }
    }

    #pragma unroll
    for (int m = 0; m < 8; m++) {
        int node = nodeBase + warp * 8 + m;
        if (node < n) g_h[(size_t)node * HID + lane] = acc[m];   // raw, unscaled
    }
}

// ---------------------------------------------------------------------------
// K-scale: h' = rsqrt(deg) * h_raw (in place);  A = h'  (self-loop absorbed).
// One thread per float4: 8 threads per node.
__global__ void __launch_bounds__(256) k_scale(int n) {
    int i = blockIdx.x * blockDim.x + threadIdx.x;
    if (i >= n * 8) return;
    int node = i >> 3;
    float dinv = rsqrtf(g_deg[node]);
    float4* h4 = (float4*)g_h;
    float4* a4 = (float4*)g_A;
    float4 v = h4[i];
    v.x *= dinv; v.y *= dinv; v.z *= dinv; v.w *= dinv;
    h4[i] = v;
    a4[i] = v;
}

// ---------------------------------------------------------------------------
// K3: edge scatter.  A[dst] += w * h'[src]  -- 8 threads per edge, float4 each.
// Native float4 atomicAdd (sm_90+) -> 128-bit RED, quarter the LTS atomic ops.
__global__ void __launch_bounds__(256) k_edge(const float* __restrict__ ew, int E) {
    long long t = (long long)blockIdx.x * blockDim.x + threadIdx.x;
    if (t >= (long long)E * 8) return;
    int e = (int)(t >> 3);
    int c = (int)(t & 7);

    int2 sd = __ldg(&g_sd[e]);          // broadcast across the 8 threads of this edge
    float w = __ldg(&ew[e]);

    const float4* hp = (const float4*)g_h;
    float4 hv = __ldg(&hp[(size_t)sd.x * 8 + c]);

    float4* ap = reinterpret_cast<float4*>(g_A) + ((size_t)sd.y * 8 + c);
    atomicAdd(ap, make_float4(w * hv.x, w * hv.y, w * hv.z, w * hv.w));
}

// ---------------------------------------------------------------------------
// K4: out[n] = relu(dinv[n]*A[n][:] + b1) . W2 + b2    (warp per node)
__global__ void __launch_bounds__(256) k_final(const float* __restrict__ b1,
                                               const float* __restrict__ W2,
                                               const float* __restrict__ b2,
                                               float* __restrict__ out, int n) {
    int gwarp = (blockIdx.x * blockDim.x + threadIdx.x) >> 5;
    int lane = threadIdx.x & 31;
    if (gwarp >= n) return;
    float dinv = rsqrtf(g_deg[gwarp]);
    float v = dinv * g_A[(size_t)gwarp * HID + lane] + __ldg(&b1[lane]);
    v = fmaxf(v, 0.f) * __ldg(&W2[lane]);
    #pragma unroll
    for (int o = 16; o > 0; o >>= 1) v += __shfl_xor_sync(0xffffffff, v, o);
    if (lane == 0) out[gwarp] = v + __ldg(&b2[0]);
}

// ---------------------------------------------------------------------------
extern "C" void kernel_launch(void* const* d_in, const int* in_sizes, int n_in,
                              void* d_out, int out_size) {
    const float* x  = (const float*)d_in[0];
    const void*  ei = d_in[1];
    const float* ew = (const float*)d_in[2];
    const float* W1 = (const float*)d_in[3];
    const float* b1 = (const float*)d_in[4];
    const float* W2 = (const float*)d_in[5];
    const float* b2 = (const float*)d_in[6];
    float* out = (float*)d_out;

    int n = in_sizes[0] / 128;       // N nodes
    int E = in_sizes[2];             // edges (edge_weight count)

    int G = (n + 63) / 64;           // gemm blocks
    int C = (E + 255) / 256;         // convert/deg blocks

    k_detect<<<1, 32>>>((const unsigned int*)ei);
    k_init_deg<<<(n + 255) / 256, 256>>>(n);
    k_fused<<<G + C, 256>>>(x, W1, ei, ew, n, E, G);
    k_scale<<<(n * 8 + 255) / 256, 256>>>(n);

    long long work = (long long)E * 8;
    k_edge<<<(int)((work + 255) / 256), 256>>>(ew, E);

    k_final<<<(n + 7) / 8, 256>>>(b1, W2, b2, out, n);
}